// round 5
// baseline (speedup 1.0000x reference)
#include <cuda_runtime.h>
#include <cuda_bf16.h>
#include <cstdint>

#define NMAX 100000
#define CC   128
#define EMAX 1600000
#define SCAN_B 1024

// ---------------- scratch (static device globals; no allocation) -------------
__device__ float g_h   [(size_t)NMAX * CC];   // post-GEMM features
__device__ float g_agg [(size_t)NMAX * CC];   // aggregated features
__device__ float g_dinv[NMAX];
__device__ int   g_deg [NMAX];
__device__ int   g_rowstart[NMAX + 1];
__device__ int   g_cursor[NMAX];
__device__ int   g_srcidx[EMAX];
__device__ float g_enorm [EMAX];
__device__ int   g_part[256];
__device__ int   g_partbase[256];
__device__ float g_sum[CC], g_sumsq[CC], g_scale[CC], g_shift[CC];

// ---------------- helpers -----------------------------------------------------
__device__ __forceinline__ float f2tf32(float x) {
    uint32_t u;
    asm("cvt.rna.tf32.f32 %0, %1;" : "=r"(u) : "f"(x));
    return __uint_as_float(u);
}

__device__ __forceinline__ void mma_tf32(float* c, const float* a, float b0, float b1) {
    asm volatile(
        "mma.sync.aligned.m16n8k8.row.col.f32.tf32.tf32.f32 "
        "{%0,%1,%2,%3},{%4,%5,%6,%7},{%8,%9},{%0,%1,%2,%3};"
        : "+f"(c[0]), "+f"(c[1]), "+f"(c[2]), "+f"(c[3])
        : "r"(__float_as_uint(a[0])), "r"(__float_as_uint(a[1])),
          "r"(__float_as_uint(a[2])), "r"(__float_as_uint(a[3])),
          "r"(__float_as_uint(b0)), "r"(__float_as_uint(b1)));
}

// ---------------- setup kernels ----------------------------------------------
__global__ void k_init_deg(int n) {
    int i = blockIdx.x * blockDim.x + threadIdx.x;
    if (i < n) g_deg[i] = 0;
}

__global__ void k_count(const int* __restrict__ ei, int E) {
    int e = blockIdx.x * blockDim.x + threadIdx.x;
    if (e >= E) return;
    atomicAdd(&g_deg[ei[E + e]], 1);
}

__global__ void k_dinv(int n) {
    int i = blockIdx.x * blockDim.x + threadIdx.x;
    if (i < n) g_dinv[i] = rsqrtf((float)g_deg[i] + 1.0f);
}

__global__ __launch_bounds__(SCAN_B) void k_scan1(int n) {
    __shared__ int s[SCAN_B];
    int t = threadIdx.x;
    int i = blockIdx.x * SCAN_B + t;
    int v = (i < n) ? g_deg[i] : 0;
    s[t] = v;
    __syncthreads();
#pragma unroll
    for (int off = 1; off < SCAN_B; off <<= 1) {
        int add = (t >= off) ? s[t - off] : 0;
        __syncthreads();
        s[t] += add;
        __syncthreads();
    }
    if (i < n) g_rowstart[i] = s[t] - v;
    if (t == SCAN_B - 1) g_part[blockIdx.x] = s[t];
}

__global__ void k_scan2(int nb, int n) {
    __shared__ int s[256];
    int t = threadIdx.x;
    int v = (t < nb) ? g_part[t] : 0;
    s[t] = v;
    __syncthreads();
#pragma unroll
    for (int off = 1; off < 256; off <<= 1) {
        int add = (t >= off) ? s[t - off] : 0;
        __syncthreads();
        s[t] += add;
        __syncthreads();
    }
    if (t < nb) g_partbase[t] = s[t] - v;
    if (t == 255) g_rowstart[n] = s[255];
}

__global__ __launch_bounds__(SCAN_B) void k_scan3(int n) {
    int i = blockIdx.x * SCAN_B + threadIdx.x;
    if (i >= n) return;
    int r = g_rowstart[i] + g_partbase[blockIdx.x];
    g_rowstart[i] = r;
    g_cursor[i]   = r;
}

__global__ void k_fill(const int* __restrict__ ei, int E) {
    int e = blockIdx.x * blockDim.x + threadIdx.x;
    if (e >= E) return;
    int sN = ei[e];
    int d  = ei[E + e];
    int p = atomicAdd(&g_cursor[d], 1);
    g_srcidx[p] = sN;
    g_enorm[p]  = g_dinv[sN] * g_dinv[d];
}

// ---------------- tf32 tensor-core GEMM: H = X @ W ---------------------------
// 3-term compensated tf32 (ah*bh + al*bh + ah*bl) -> fp32-class accuracy.
// Original fp32 tiles staged in SMEM; hi/lo split done in registers at
// fragment-load time. Block tile M=128 x N=128, K chunks of 32.
// 8 warps = 4(M) x 2(N); warp tile 32x64 -> 2 x 8 m16n8k8 tiles.
// A stride 36 (g*4+tg -> conflict-free), B stride 136 (tg*8+g -> conflict-free).
#define AS 36
#define BS 136
template <bool BN_FUSE>
__global__ __launch_bounds__(256, 2) void k_gemm_tf32(const float* __restrict__ X,
                                                      const float* __restrict__ W,
                                                      float* __restrict__ H, int n) {
    __shared__ float As[128 * AS];
    __shared__ float Bs[32 * BS];

    int tid = threadIdx.x;
    int wid = tid >> 5, lane = tid & 31;
    int wm = wid & 3, wn = wid >> 2;        // warp grid 4x2
    int g = lane >> 2, tg = lane & 3;       // groupID, threadID-in-group
    int br = blockIdx.x * 128;

    float acc[2][8][4];
#pragma unroll
    for (int mi = 0; mi < 2; mi++)
#pragma unroll
        for (int nj = 0; nj < 8; nj++)
#pragma unroll
            for (int j = 0; j < 4; j++) acc[mi][nj][j] = 0.f;

    for (int kt = 0; kt < 128; kt += 32) {
        // stage A chunk: 128 rows x 32 k (1024 float4, 4 per thread)
#pragma unroll
        for (int i = 0; i < 4; i++) {
            int f = tid + i * 256;
            int row = f >> 3, kc = f & 7;
            float4 v = make_float4(0.f, 0.f, 0.f, 0.f);
            int gr = br + row;
            if (gr < n) {
                v = *(const float4*)(X + (size_t)gr * 128 + kt + kc * 4);
                if (BN_FUSE) {
                    int f4 = (kt >> 2) + kc;
                    float4 sc = ((const float4*)g_scale)[f4];
                    float4 sh = ((const float4*)g_shift)[f4];
                    v.x = fmaxf(fmaf(v.x, sc.x, sh.x), 0.f);
                    v.y = fmaxf(fmaf(v.y, sc.y, sh.y), 0.f);
                    v.z = fmaxf(fmaf(v.z, sc.z, sh.z), 0.f);
                    v.w = fmaxf(fmaf(v.w, sc.w, sh.w), 0.f);
                }
            }
            float* p = As + row * AS + kc * 4;
            p[0] = v.x; p[1] = v.y; p[2] = v.z; p[3] = v.w;
        }
        // stage B chunk: 32 k x 128 n (1024 float4, 4 per thread)
#pragma unroll
        for (int i = 0; i < 4; i++) {
            int f = tid + i * 256;
            int kr = f >> 5, c4 = f & 31;
            float4 v = *(const float4*)(W + (size_t)(kt + kr) * 128 + c4 * 4);
            float* p = Bs + kr * BS + c4 * 4;
            p[0] = v.x; p[1] = v.y; p[2] = v.z; p[3] = v.w;
        }
        __syncthreads();

#pragma unroll
        for (int s2 = 0; s2 < 4; s2++) {
            int kb = s2 * 8;
            float ah[2][4], al[2][4];
#pragma unroll
            for (int mi = 0; mi < 2; mi++) {
                int r0 = wm * 32 + mi * 16 + g;
                float a0 = As[r0 * AS + kb + tg];
                float a1 = As[(r0 + 8) * AS + kb + tg];
                float a2 = As[r0 * AS + kb + tg + 4];
                float a3 = As[(r0 + 8) * AS + kb + tg + 4];
                ah[mi][0] = f2tf32(a0); al[mi][0] = f2tf32(a0 - ah[mi][0]);
                ah[mi][1] = f2tf32(a1); al[mi][1] = f2tf32(a1 - ah[mi][1]);
                ah[mi][2] = f2tf32(a2); al[mi][2] = f2tf32(a2 - ah[mi][2]);
                ah[mi][3] = f2tf32(a3); al[mi][3] = f2tf32(a3 - ah[mi][3]);
            }
#pragma unroll
            for (int nj = 0; nj < 8; nj++) {
                int nb = wn * 64 + nj * 8 + g;
                float b0 = Bs[(kb + tg) * BS + nb];
                float b1 = Bs[(kb + tg + 4) * BS + nb];
                float bh0 = f2tf32(b0), bl0 = f2tf32(b0 - bh0);
                float bh1 = f2tf32(b1), bl1 = f2tf32(b1 - bh1);
#pragma unroll
                for (int mi = 0; mi < 2; mi++) {
                    mma_tf32(acc[mi][nj], ah[mi], bh0, bh1);
                    mma_tf32(acc[mi][nj], al[mi], bh0, bh1);
                    mma_tf32(acc[mi][nj], ah[mi], bl0, bl1);
                }
            }
        }
        __syncthreads();
    }

    // epilogue: c0,c1 at (row g, cols 2tg,2tg+1); c2,c3 at row g+8
#pragma unroll
    for (int mi = 0; mi < 2; mi++) {
        int row = br + wm * 32 + mi * 16 + g;
#pragma unroll
        for (int nj = 0; nj < 8; nj++) {
            int col = wn * 64 + nj * 8 + 2 * tg;
            if (row < n)
                *(float2*)(H + (size_t)row * 128 + col) =
                    make_float2(acc[mi][nj][0], acc[mi][nj][1]);
            if (row + 8 < n)
                *(float2*)(H + (size_t)(row + 8) * 128 + col) =
                    make_float2(acc[mi][nj][2], acc[mi][nj][3]);
        }
    }
}

// ---------------- CSR gather aggregation + fused BN stats ---------------------
__global__ __launch_bounds__(256) void k_agg_stats(const float* __restrict__ H,
                                                   const float* __restrict__ b,
                                                   float* __restrict__ AGG,
                                                   int n, int totalWarps) {
    __shared__ float ssum[8][128];
    __shared__ float ssq [8][128];
    int wid = threadIdx.x >> 5;
    int lane = threadIdx.x & 31;
    int w = blockIdx.x * 8 + wid;

    float4 bv = ((const float4*)b)[lane];
    float4 ls = make_float4(0.f, 0.f, 0.f, 0.f);
    float4 lq = make_float4(0.f, 0.f, 0.f, 0.f);

    for (int v = w; v < n; v += totalWarps) {
        float dinv = g_dinv[v];
        float self = dinv * dinv;
        float4 hv = *(const float4*)(H + (size_t)v * 128 + lane * 4);
        float4 acc;
        acc.x = hv.x * self + bv.x;
        acc.y = hv.y * self + bv.y;
        acc.z = hv.z * self + bv.z;
        acc.w = hv.w * self + bv.w;

        int rs = g_rowstart[v], re = g_rowstart[v + 1];
        int e = rs;
        for (; e + 2 <= re; e += 2) {
            int s0 = g_srcidx[e], s1 = g_srcidx[e + 1];
            float n0 = g_enorm[e], n1 = g_enorm[e + 1];
            float4 h0 = *(const float4*)(H + (size_t)s0 * 128 + lane * 4);
            float4 h1 = *(const float4*)(H + (size_t)s1 * 128 + lane * 4);
            acc.x += h0.x * n0 + h1.x * n1;
            acc.y += h0.y * n0 + h1.y * n1;
            acc.z += h0.z * n0 + h1.z * n1;
            acc.w += h0.w * n0 + h1.w * n1;
        }
        if (e < re) {
            int s0 = g_srcidx[e];
            float n0 = g_enorm[e];
            float4 h0 = *(const float4*)(H + (size_t)s0 * 128 + lane * 4);
            acc.x += h0.x * n0;
            acc.y += h0.y * n0;
            acc.z += h0.z * n0;
            acc.w += h0.w * n0;
        }
        *(float4*)(AGG + (size_t)v * 128 + lane * 4) = acc;

        ls.x += acc.x; ls.y += acc.y; ls.z += acc.z; ls.w += acc.w;
        lq.x += acc.x * acc.x; lq.y += acc.y * acc.y;
        lq.z += acc.z * acc.z; lq.w += acc.w * acc.w;
    }

    *(float4*)&ssum[wid][lane * 4] = ls;
    *(float4*)&ssq [wid][lane * 4] = lq;
    __syncthreads();
    int t = threadIdx.x;
    if (t < 128) {
        float s = 0.f, q = 0.f;
#pragma unroll
        for (int r = 0; r < 8; r++) { s += ssum[r][t]; q += ssq[r][t]; }
        atomicAdd(&g_sum[t], s);
        atomicAdd(&g_sumsq[t], q);
    }
}

// ---------------- batchnorm finalize / apply ----------------------------------
__global__ void k_zero_stats() {
    int c = threadIdx.x;
    g_sum[c] = 0.f;
    g_sumsq[c] = 0.f;
}

__global__ void k_bn_final(const float* __restrict__ gamma,
                           const float* __restrict__ beta, int n) {
    int c = threadIdx.x;
    float invn = 1.0f / (float)n;
    float m = g_sum[c] * invn;
    float var = g_sumsq[c] * invn - m * m;
    float rstd = rsqrtf(var + 1e-5f);
    float sc = gamma[c] * rstd;
    g_scale[c] = sc;
    g_shift[c] = beta[c] - m * sc;
}

// y = relu(a*scale + shift + x)   (residual; final output)
__global__ void k_apply_relu_res(const float* __restrict__ A,
                                 const float* __restrict__ X,
                                 float* __restrict__ O, int total4) {
    int i = blockIdx.x * blockDim.x + threadIdx.x;
    if (i >= total4) return;
    int c4 = i & 31;
    float4 sc = ((const float4*)g_scale)[c4];
    float4 sh = ((const float4*)g_shift)[c4];
    float4 a = ((const float4*)A)[i];
    float4 x = ((const float4*)X)[i];
    float4 o;
    o.x = fmaxf(fmaf(a.x, sc.x, sh.x) + x.x, 0.f);
    o.y = fmaxf(fmaf(a.y, sc.y, sh.y) + x.y, 0.f);
    o.z = fmaxf(fmaf(a.z, sc.z, sh.z) + x.z, 0.f);
    o.w = fmaxf(fmaf(a.w, sc.w, sh.w) + x.w, 0.f);
    ((float4*)O)[i] = o;
}

// ---------------- launch ------------------------------------------------------
extern "C" void kernel_launch(void* const* d_in, const int* in_sizes, int n_in,
                              void* d_out, int out_size) {
    const float* x     = (const float*)d_in[0];
    const float* W1    = (const float*)d_in[1];
    const float* b1    = (const float*)d_in[2];
    const float* W2    = (const float*)d_in[3];
    const float* b2    = (const float*)d_in[4];
    const float* gamma = (const float*)d_in[5];
    const float* beta  = (const float*)d_in[6];
    const int*   ei    = (const int*)d_in[7];   // int32 [2, E]

    int n = in_sizes[0] / CC;
    int E = in_sizes[7] / 2;
    float* out = (float*)d_out;

    float *p_h, *p_agg;
    cudaGetSymbolAddress((void**)&p_h,   g_h);
    cudaGetSymbolAddress((void**)&p_agg, g_agg);

    int nb_n  = (n + 255) / 256;
    int nb_e  = (E + 255) / 256;
    int nb_sc = (n + SCAN_B - 1) / SCAN_B;
    int total4 = n * (CC / 4);
    int nb_4  = (total4 + 255) / 256;
    int nb_gemm = (n + 127) / 128;
    int agg_blocks = 1184;
    int agg_warps = agg_blocks * 8;

    // --- CSR setup (shared by both layers) ---
    k_init_deg<<<nb_n, 256>>>(n);
    k_count<<<nb_e, 256>>>(ei, E);
    k_dinv<<<nb_n, 256>>>(n);
    k_scan1<<<nb_sc, SCAN_B>>>(n);
    k_scan2<<<1, 256>>>(nb_sc, n);
    k_scan3<<<nb_sc, SCAN_B>>>(n);
    k_fill<<<nb_e, 256>>>(ei, E);

    // --- layer 1 ---
    k_gemm_tf32<false><<<nb_gemm, 256>>>(x, W1, p_h, n);
    k_zero_stats<<<1, 128>>>();
    k_agg_stats<<<agg_blocks, 256>>>(p_h, b1, p_agg, n, agg_warps);
    k_bn_final<<<1, 128>>>(gamma, beta, n);

    // --- layer 2 (BN+ReLU of layer 1 fused into GEMM A-load) ---
    k_gemm_tf32<true><<<nb_gemm, 256>>>(p_agg, W2, p_h, n);
    k_zero_stats<<<1, 128>>>();
    k_agg_stats<<<agg_blocks, 256>>>(p_h, b2, p_agg, n, agg_warps);
    k_bn_final<<<1, 128>>>(gamma, beta, n);
    k_apply_relu_res<<<nb_4, 256>>>(p_agg, x, out, total4);
}